// round 7
// baseline (speedup 1.0000x reference)
#include <cuda_runtime.h>
#include <cuda_bf16.h>

#define NN 10000
#define RP 16
#define EE 64
#define NTT 8000
#define RR 8000
#define CC 16
#define NREL 50

// ---- static scratch (no allocations) ----
__device__ float g_T1[NREL * RP];
__device__ float g_T2[NREL * RP];
__device__ int   g_p[NTT];
__device__ float g_colsum[NN * RP];
__device__ float g_rowsum[NN * RP];
__device__ float g_h[NN * EE];
__device__ float g_P[NN * RP * CC];   // P[n][r2*16+c]

// K0: zero sums/h, init out = bias2
__global__ void k_zero(const float* __restrict__ bias2, float* __restrict__ out) {
    int i = blockIdx.x * blockDim.x + threadIdx.x;
    if (i < NN * RP) { g_colsum[i] = 0.f; g_rowsum[i] = 0.f; }
    if (i < NN * EE) g_h[i] = 0.f;
    if (i < NN * CC) out[i] = bias2[i & (CC - 1)];
}

// K1: latent tables for the 50 possible one-hot inputs. warp per p, grid 50.
__global__ void k_table(const float* __restrict__ w1a, const float* __restrict__ b1a,
                        const float* __restrict__ w1b, const float* __restrict__ b1b,
                        const float* __restrict__ w2a, const float* __restrict__ b2a,
                        const float* __restrict__ w2b, const float* __restrict__ b2b) {
    int p = blockIdx.x;
    int lane = threadIdx.x;
    float a0 = fmaxf(w1a[p * EE + lane] + b1a[lane], 0.f);
    float a1 = fmaxf(w1a[p * EE + 32 + lane] + b1a[32 + lane], 0.f);
    float c0 = fmaxf(w2a[p * EE + lane] + b2a[lane], 0.f);
    float c1 = fmaxf(w2a[p * EE + 32 + lane] + b2a[32 + lane], 0.f);
    float y1[RP], y2[RP];
#pragma unroll
    for (int r = 0; r < RP; r++) {
        y1[r] = a0 * w1b[lane * RP + r] + a1 * w1b[(lane + 32) * RP + r];
        y2[r] = c0 * w2b[lane * RP + r] + c1 * w2b[(lane + 32) * RP + r];
    }
#pragma unroll
    for (int off = 16; off >= 1; off >>= 1) {
#pragma unroll
        for (int r = 0; r < RP; r++) {
            y1[r] += __shfl_xor_sync(0xffffffffu, y1[r], off);
            y2[r] += __shfl_xor_sync(0xffffffffu, y2[r], off);
        }
    }
    float m1 = -1e30f, m2 = -1e30f;
#pragma unroll
    for (int r = 0; r < RP; r++) {
        y1[r] += b1b[r]; y2[r] += b2b[r];
        m1 = fmaxf(m1, y1[r]); m2 = fmaxf(m2, y2[r]);
    }
    float s1 = 0.f, s2 = 0.f, e1 = 0.f, e2 = 0.f;
#pragma unroll
    for (int r = 0; r < RP; r++) {
        float t1 = __expf(y1[r] - m1), t2 = __expf(y2[r] - m2);
        s1 += t1; s2 += t2;
        if (lane == r) { e1 = t1; e2 = t2; }
    }
    if (lane < RP) {
        g_T1[p * RP + lane] = e1 / s1;
        g_T2[p * RP + lane] = e2 / s2;
    }
}

// K2: find p[t] from nhots; accumulate colsum/rowsum (index-0 hotspot pre-reduced)
__global__ void k_sums(const float* __restrict__ nhots, const int* __restrict__ hind) {
    int t = blockIdx.x * blockDim.x + threadIdx.x;
    float c0 = 0.f, r0 = 0.f;
    if (t < NTT) {
        const float* row = nhots + (long long)t * RR;
        int p = 0;
#pragma unroll
        for (int j = 0; j < NREL; j++)
            if (row[j] != 0.f) p = j;
        g_p[t] = p;
        int s = hind[2 * (NTT + t)];
        int o = hind[2 * (NTT + t) + 1];
#pragma unroll
        for (int r = 0; r < RP; r++) {
            float l1 = g_T1[p * RP + r], l2 = g_T2[p * RP + r];
            int ic = o * r, ir = s * r;
            if (ic) atomicAdd(&g_colsum[ic], l1); else c0 += l1;
            if (ir) atomicAdd(&g_rowsum[ir], l2); else r0 += l2;
        }
    }
#pragma unroll
    for (int off = 16; off >= 1; off >>= 1) {
        c0 += __shfl_xor_sync(0xffffffffu, c0, off);
        r0 += __shfl_xor_sync(0xffffffffu, r0, off);
    }
    if ((threadIdx.x & 31) == 0) {
        if (c0 != 0.f) atomicAdd(&g_colsum[0], c0);
        if (r0 != 0.f) atomicAdd(&g_rowsum[0], r0);
    }
}

// K3: h[s] += (L1/colsum) * weights1_flat[o*r]. warp per t.
__global__ void k_hacc(const int* __restrict__ hind, const float* __restrict__ w1) {
    __shared__ float sT1[NREL * RP];
    for (int i = threadIdx.x; i < NREL * RP; i += blockDim.x) sT1[i] = g_T1[i];
    __syncthreads();
    int warp = threadIdx.x >> 5, lane = threadIdx.x & 31;
    int t = blockIdx.x * 8 + warp;
    if (t >= NTT) return;
    int p = g_p[t];
    int s = hind[2 * (NTT + t)];
    int o = hind[2 * (NTT + t) + 1];
    float acc0 = 0.f, acc1 = 0.f;
#pragma unroll
    for (int r = 0; r < RP; r++) {
        int idx = o * r;
        float w = sT1[p * RP + r] / g_colsum[idx];
        const float* row = w1 + (size_t)idx * EE;
        acc0 += w * row[lane];
        acc1 += w * row[lane + 32];
    }
    atomicAdd(&g_h[s * EE + lane], acc0);
    atomicAdd(&g_h[s * EE + 32 + lane], acc1);
}

// K4: h = relu(h + bias1)
__global__ void k_hpost(const float* __restrict__ bias1) {
    int i = blockIdx.x * blockDim.x + threadIdx.x;
    if (i < NN * EE) g_h[i] = fmaxf(g_h[i] + bias1[i & (EE - 1)], 0.f);
}

// K5: P = h(10000x64) @ B(64x256), B[k][r2*16+c] = weights2[r2,k,c]
__global__ void k_gemm(const float* __restrict__ w2) {
    __shared__ float sA[64][65];
    __shared__ float sB[64][64];
    int tid = threadIdx.x;
    int rb = blockIdx.x, cb = blockIdx.y;
    for (int idx = tid; idx < 64 * 64; idx += 256) {
        int i = idx >> 6, k = idx & 63;
        int gr = rb * 64 + i;
        sA[i][k] = (gr < NN) ? g_h[gr * 64 + k] : 0.f;
    }
    for (int idx = tid; idx < 64 * 64; idx += 256) {
        int k = idx >> 6, j = idx & 63;
        int col = cb * 64 + j;
        sB[k][j] = w2[((col >> 4) * 64 + k) * 16 + (col & 15)];
    }
    __syncthreads();
    int tx = tid & 15, ty = tid >> 4;
    float acc[4][4] = {};
#pragma unroll
    for (int k = 0; k < 64; k++) {
        float a[4];
#pragma unroll
        for (int i = 0; i < 4; i++) a[i] = sA[ty * 4 + i][k];
        float4 bv = *(const float4*)&sB[k][tx * 4];
        float b[4] = {bv.x, bv.y, bv.z, bv.w};
#pragma unroll
        for (int i = 0; i < 4; i++)
#pragma unroll
            for (int j = 0; j < 4; j++) acc[i][j] += a[i] * b[j];
    }
#pragma unroll
    for (int i = 0; i < 4; i++) {
        int gr = rb * 64 + ty * 4 + i;
        if (gr < NN)
            *(float4*)&g_P[gr * 256 + cb * 64 + tx * 4] =
                make_float4(acc[i][0], acc[i][1], acc[i][2], acc[i][3]);
    }
}

// K6: scatter out[n',c] += (L2/rowsum) * P[o, r2, c]; flat==0 hotspot block-reduced.
// 16 threads per t (c-parallel), 16 t per block.
__global__ void k_scatter(const int* __restrict__ hind, float* __restrict__ out) {
    __shared__ float sT2[NREL * RP];
    __shared__ float red[256];
    for (int i = threadIdx.x; i < NREL * RP; i += 256) sT2[i] = g_T2[i];
    __syncthreads();
    int tid = threadIdx.x;
    int tt = tid >> 4, c = tid & 15;
    int t = blockIdx.x * 16 + tt;
    int p = g_p[t];
    int s = hind[2 * (NTT + t)];
    int o = hind[2 * (NTT + t) + 1];
    const float* Po = g_P + (size_t)o * 256;
    float acc0 = 0.f;
#pragma unroll
    for (int r = 0; r < RP; r++) {
        int flat = s * r;
        float w = sT2[p * RP + r] / g_rowsum[flat];
        int r2 = flat / NN;
        int np = flat - r2 * NN;
        float val = w * Po[r2 * 16 + c];
        if (flat == 0) acc0 += val;
        else atomicAdd(&out[np * CC + c], val);
    }
    red[tid] = acc0;
    __syncthreads();
    if (tt == 0) {
        float ssum = 0.f;
#pragma unroll
        for (int i = 0; i < 16; i++) ssum += red[i * 16 + c];
        atomicAdd(&out[c], ssum);
    }
}

extern "C" void kernel_launch(void* const* d_in, const int* in_sizes, int n_in,
                              void* d_out, int out_size) {
    const float* nhots = (const float*)d_in[0];
    const float* w1a = (const float*)d_in[1];
    const float* b1a = (const float*)d_in[2];
    const float* w1b = (const float*)d_in[3];
    const float* b1b = (const float*)d_in[4];
    const float* w2a = (const float*)d_in[5];
    const float* b2a = (const float*)d_in[6];
    const float* w2b = (const float*)d_in[7];
    const float* b2b = (const float*)d_in[8];
    const float* weights1 = (const float*)d_in[9];
    const float* bias1 = (const float*)d_in[10];
    const float* weights2 = (const float*)d_in[11];
    const float* bias2 = (const float*)d_in[12];
    const int* hind = (const int*)d_in[13];
    float* out = (float*)d_out;

    k_zero<<<(NN * EE + 255) / 256, 256>>>(bias2, out);
    k_table<<<NREL, 32>>>(w1a, b1a, w1b, b1b, w2a, b2a, w2b, b2b);
    k_sums<<<(NTT + 255) / 256, 256>>>(nhots, hind);
    k_hacc<<<NTT / 8, 256>>>(hind, weights1);
    k_hpost<<<(NN * EE + 255) / 256, 256>>>(bias1);
    dim3 gg((NN + 63) / 64, 4);
    k_gemm<<<gg, 256>>>(weights2);
    k_scatter<<<NTT / 16, 256>>>(hind, out);
}

// round 8
// speedup vs baseline: 1.4134x; 1.4134x over previous
#include <cuda_runtime.h>
#include <cuda_bf16.h>

#define NN 10000
#define RP 16
#define EE 64
#define NTT 8000
#define RR 8000
#define CC 16
#define NREL 50

// ---- static scratch (no allocations) ----
__device__ float g_T1[NREL * RP];
__device__ float g_T2[NREL * RP];
__device__ int   g_p[NTT];
__device__ float g_colsum[NN * RP];
__device__ float g_rowsum[NN * RP];
__device__ float g_h[NN * EE];
__device__ float g_P[NN * RP * CC];   // P[n][r2*16+c]

// K0: zero sums/h, init out = bias2; blocks 0..49 also build latent tables.
__global__ void k_zero(const float* __restrict__ bias2, float* __restrict__ out,
                       const float* __restrict__ w1a, const float* __restrict__ b1a,
                       const float* __restrict__ w1b, const float* __restrict__ b1b,
                       const float* __restrict__ w2a, const float* __restrict__ b2a,
                       const float* __restrict__ w2b, const float* __restrict__ b2b) {
    int i = blockIdx.x * blockDim.x + threadIdx.x;
    if (i < NN * RP) { g_colsum[i] = 0.f; g_rowsum[i] = 0.f; }
    if (i < NN * EE) g_h[i] = 0.f;
    if (i < NN * CC) out[i] = bias2[i & (CC - 1)];

    // latent tables: one warp (warp 0 of blocks 0..49) per hot index p
    if (blockIdx.x < NREL && threadIdx.x < 32) {
        int p = blockIdx.x;
        int lane = threadIdx.x;
        float a0 = fmaxf(w1a[p * EE + lane] + b1a[lane], 0.f);
        float a1 = fmaxf(w1a[p * EE + 32 + lane] + b1a[32 + lane], 0.f);
        float c0 = fmaxf(w2a[p * EE + lane] + b2a[lane], 0.f);
        float c1 = fmaxf(w2a[p * EE + 32 + lane] + b2a[32 + lane], 0.f);
        float y1[RP], y2[RP];
#pragma unroll
        for (int r = 0; r < RP; r++) {
            y1[r] = a0 * w1b[lane * RP + r] + a1 * w1b[(lane + 32) * RP + r];
            y2[r] = c0 * w2b[lane * RP + r] + c1 * w2b[(lane + 32) * RP + r];
        }
#pragma unroll
        for (int off = 16; off >= 1; off >>= 1) {
#pragma unroll
            for (int r = 0; r < RP; r++) {
                y1[r] += __shfl_xor_sync(0xffffffffu, y1[r], off);
                y2[r] += __shfl_xor_sync(0xffffffffu, y2[r], off);
            }
        }
        float m1 = -1e30f, m2 = -1e30f;
#pragma unroll
        for (int r = 0; r < RP; r++) {
            y1[r] += b1b[r]; y2[r] += b2b[r];
            m1 = fmaxf(m1, y1[r]); m2 = fmaxf(m2, y2[r]);
        }
        float s1 = 0.f, s2 = 0.f, e1 = 0.f, e2 = 0.f;
#pragma unroll
        for (int r = 0; r < RP; r++) {
            float t1 = __expf(y1[r] - m1), t2 = __expf(y2[r] - m2);
            s1 += t1; s2 += t2;
            if (lane == r) { e1 = t1; e2 = t2; }
        }
        if (lane < RP) {
            g_T1[p * RP + lane] = e1 / s1;
            g_T2[p * RP + lane] = e2 / s2;
        }
    }
}

// K2: find p[t] (float4 scan of first 50 cols); accumulate colsum/rowsum.
__global__ void k_sums(const float* __restrict__ nhots, const int* __restrict__ hind) {
    int t = blockIdx.x * blockDim.x + threadIdx.x;
    float c0 = 0.f, r0 = 0.f;
    if (t < NTT) {
        const float4* row4 = (const float4*)(nhots + (size_t)t * RR);
        int p = 0;
#pragma unroll
        for (int j = 0; j < 12; j++) {
            float4 v = row4[j];
            if (v.x != 0.f) p = 4 * j;
            if (v.y != 0.f) p = 4 * j + 1;
            if (v.z != 0.f) p = 4 * j + 2;
            if (v.w != 0.f) p = 4 * j + 3;
        }
        {
            float4 v = row4[12];
            if (v.x != 0.f) p = 48;
            if (v.y != 0.f) p = 49;
        }
        g_p[t] = p;
        int s = hind[2 * (NTT + t)];
        int o = hind[2 * (NTT + t) + 1];
#pragma unroll
        for (int r = 0; r < RP; r++) {
            float l1 = g_T1[p * RP + r], l2 = g_T2[p * RP + r];
            int ic = o * r, ir = s * r;
            if (ic) atomicAdd(&g_colsum[ic], l1); else c0 += l1;
            if (ir) atomicAdd(&g_rowsum[ir], l2); else r0 += l2;
        }
    }
#pragma unroll
    for (int off = 16; off >= 1; off >>= 1) {
        c0 += __shfl_xor_sync(0xffffffffu, c0, off);
        r0 += __shfl_xor_sync(0xffffffffu, r0, off);
    }
    if ((threadIdx.x & 31) == 0) {
        if (c0 != 0.f) atomicAdd(&g_colsum[0], c0);
        if (r0 != 0.f) atomicAdd(&g_rowsum[0], r0);
    }
}

// K3: h[s] += (L1/colsum)*weights1_flat[o*r]. Warp per t; half-warp per r,
// float4 lanes -> 8 fully-unrolled iterations, 8 LDG.128 in flight per lane.
__global__ void k_hacc(const int* __restrict__ hind, const float* __restrict__ w1) {
    __shared__ float sT1[NREL * RP];
    for (int i = threadIdx.x; i < NREL * RP; i += blockDim.x) sT1[i] = g_T1[i];
    __syncthreads();
    int warp = threadIdx.x >> 5, lane = threadIdx.x & 31;
    int t = blockIdx.x * 8 + warp;
    int half = lane >> 4;      // 0 -> even r, 1 -> odd r
    int q = lane & 15;         // float4 slot within the 64-float row
    int p = g_p[t];
    int s = hind[2 * (NTT + t)];
    int o = hind[2 * (NTT + t) + 1];
    float ax = 0.f, ay = 0.f, az = 0.f, aw = 0.f;
#pragma unroll
    for (int i = 0; i < 8; i++) {
        int r = 2 * i + half;
        int idx = o * r;
        float w = __fdividef(sT1[p * RP + r], g_colsum[idx]);
        float4 v = ((const float4*)(w1 + (size_t)idx * EE))[q];
        ax += w * v.x; ay += w * v.y; az += w * v.z; aw += w * v.w;
    }
    // combine even/odd halves (both cover columns q*4..q*4+3)
    ax += __shfl_xor_sync(0xffffffffu, ax, 16);
    ay += __shfl_xor_sync(0xffffffffu, ay, 16);
    az += __shfl_xor_sync(0xffffffffu, az, 16);
    aw += __shfl_xor_sync(0xffffffffu, aw, 16);
    if (half == 0) {
        float* dst = &g_h[s * EE + q * 4];
        atomicAdd(dst + 0, ax);
        atomicAdd(dst + 1, ay);
        atomicAdd(dst + 2, az);
        atomicAdd(dst + 3, aw);
    }
}

// K5: P = relu(h+bias1)(10000x64) @ B(64x256); B[k][r2*16+c] = weights2[r2,k,c]
__global__ void k_gemm(const float* __restrict__ w2, const float* __restrict__ bias1) {
    __shared__ float sAT[64][68];   // transposed A tile, padded for aligned float4
    __shared__ float sB[64][64];
    int tid = threadIdx.x;
    int rb = blockIdx.x, cb = blockIdx.y;
    for (int idx = tid; idx < 64 * 64; idx += 256) {
        int i = idx >> 6, k = idx & 63;
        int gr = rb * 64 + i;
        float hv = (gr < NN) ? fmaxf(g_h[gr * 64 + k] + bias1[k], 0.f) : 0.f;
        sAT[k][i] = hv;
    }
    for (int idx = tid; idx < 64 * 64; idx += 256) {
        int k = idx >> 6, j = idx & 63;
        int col = cb * 64 + j;
        sB[k][j] = w2[((col >> 4) * 64 + k) * 16 + (col & 15)];
    }
    __syncthreads();
    int tx = tid & 15, ty = tid >> 4;
    float acc[4][4] = {};
#pragma unroll
    for (int k = 0; k < 64; k++) {
        float4 av = *(const float4*)&sAT[k][ty * 4];
        float4 bv = *(const float4*)&sB[k][tx * 4];
        float a[4] = {av.x, av.y, av.z, av.w};
        float b[4] = {bv.x, bv.y, bv.z, bv.w};
#pragma unroll
        for (int i = 0; i < 4; i++)
#pragma unroll
            for (int j = 0; j < 4; j++) acc[i][j] += a[i] * b[j];
    }
#pragma unroll
    for (int i = 0; i < 4; i++) {
        int gr = rb * 64 + ty * 4 + i;
        if (gr < NN)
            *(float4*)&g_P[gr * 256 + cb * 64 + tx * 4] =
                make_float4(acc[i][0], acc[i][1], acc[i][2], acc[i][3]);
    }
}

// K6: out[np,c] += (L2/rowsum)*P[o,r2,c]. 16 lanes (c) per t, 16 t per block.
// P[o] block (1KB) preloaded into 16 regs; weights computed once and shuffled.
__global__ void k_scatter(const int* __restrict__ hind, float* __restrict__ out) {
    __shared__ float sT2[NREL * RP];
    __shared__ float red[256];
    for (int i = threadIdx.x; i < NREL * RP; i += 256) sT2[i] = g_T2[i];
    __syncthreads();
    int tid = threadIdx.x;
    int tt = tid >> 4, c = tid & 15;
    int half = tt & 1;               // which half of the warp this t occupies
    int t = blockIdx.x * 16 + tt;
    int p = g_p[t];
    int s = hind[2 * (NTT + t)];
    int o = hind[2 * (NTT + t) + 1];
    // lane c computes the normalization weight for r = c
    float w_mine = __fdividef(sT2[p * RP + c], g_rowsum[s * c]);
    // preload the whole P[o] block: pv[r2] = P[o][r2*16 + c]
    const float* Po = g_P + (size_t)o * 256;
    float pv[RP];
#pragma unroll
    for (int r2 = 0; r2 < RP; r2++) pv[r2] = Po[r2 * 16 + c];

    float acc0 = 0.f;
#pragma unroll
    for (int r = 0; r < RP; r++) {
        float w = __shfl_sync(0xffffffffu, w_mine, half * 16 + r);
        int flat = s * r;
        int r2 = flat / NN;
        int np = flat - r2 * NN;
        float val = w * pv[r2];
        if (flat == 0) acc0 += val;                 // r==0 or s==0 hotspot
        else atomicAdd(&out[np * CC + c], val);
    }
    red[tid] = acc0;
    __syncthreads();
    if (tt == 0) {
        float ssum = 0.f;
#pragma unroll
        for (int i = 0; i < 16; i++) ssum += red[i * 16 + c];
        atomicAdd(&out[c], ssum);
    }
}

extern "C" void kernel_launch(void* const* d_in, const int* in_sizes, int n_in,
                              void* d_out, int out_size) {
    const float* nhots = (const float*)d_in[0];
    const float* w1a = (const float*)d_in[1];
    const float* b1a = (const float*)d_in[2];
    const float* w1b = (const float*)d_in[3];
    const float* b1b = (const float*)d_in[4];
    const float* w2a = (const float*)d_in[5];
    const float* b2a = (const float*)d_in[6];
    const float* w2b = (const float*)d_in[7];
    const float* b2b = (const float*)d_in[8];
    const float* weights1 = (const float*)d_in[9];
    const float* bias1 = (const float*)d_in[10];
    const float* weights2 = (const float*)d_in[11];
    const float* bias2 = (const float*)d_in[12];
    const int* hind = (const int*)d_in[13];
    float* out = (float*)d_out;

    k_zero<<<(NN * EE + 255) / 256, 256>>>(bias2, out, w1a, b1a, w1b, b1b,
                                           w2a, b2a, w2b, b2b);
    k_sums<<<(NTT + 255) / 256, 256>>>(nhots, hind);
    k_hacc<<<NTT / 8, 256>>>(hind, weights1);
    dim3 gg((NN + 63) / 64, 4);
    k_gemm<<<gg, 256>>>(weights2, bias1);
    k_scatter<<<NTT / 16, 256>>>(hind, out);
}